// round 15
// baseline (speedup 1.0000x reference)
#include <cuda_runtime.h>
#include <cuda_fp16.h>
#include <math.h>

#define NN 100000
#define EE 1600000
#define HC 64
#define IN_DIM 128

// ---------------- scratch (device globals, allocation-free) ----------------
// g_xph holds xp in fp16 interleaved-pair layout:
//   half2 slot c (c=0..31) of node v = (xp[v][c], xp[v][c+32])
static __device__ __half2 g_xph[(size_t)NN * 32];
static __device__ float4 g_as4[NN];               // a_src [N,4]
static __device__ float4 g_dpk[2 * NN];           // [2d]=a_dst, [2d+1]=rcp (adjacent gathers)
static __device__ int    g_cnt[NN];               // degree histogram (zero-invariant between calls)
static __device__ int    g_fill[NN];              // absolute fill cursors (init to row start)
static __device__ int    g_rowptr[NN + 1];        // CSR row pointers
static __device__ int    g_bsum[512];             // scan partials
static __device__ int2   g_csr2[EE];              // CSR {src, edge_id}

__device__ __forceinline__ float lrelu(float v) { return v >= 0.f ? v : 0.2f * v; }

__device__ __forceinline__ float f2tf(float f) {
    unsigned u;
    asm("cvt.rna.tf32.f32 %0, %1;" : "=r"(u) : "f"(f));
    return __uint_as_float(u);
}
__device__ __forceinline__ void mma_tf32(float4& d,
    float a0, float a1, float a2, float a3, float b0, float b1)
{
    asm("mma.sync.aligned.m16n8k8.row.col.f32.tf32.tf32.f32 "
        "{%0,%1,%2,%3}, {%4,%5,%6,%7}, {%8,%9}, {%0,%1,%2,%3};"
        : "+f"(d.x), "+f"(d.y), "+f"(d.z), "+f"(d.w)
        : "r"(__float_as_uint(a0)), "r"(__float_as_uint(a1)),
          "r"(__float_as_uint(a2)), "r"(__float_as_uint(a3)),
          "r"(__float_as_uint(b0)), "r"(__float_as_uint(b1)));
}

// ---------------- GEMM: xp = x @ W via tf32 tensor cores + attn/fp16 epilogue ----------
__global__ __launch_bounds__(256) void gemm_kernel(
    const float* __restrict__ x, const float* __restrict__ W,
    const float* __restrict__ att_src, const float* __restrict__ att_dst, int n)
{
    __shared__ float xs[64 * 68];   // [row][k-half], stride 68 (reused for C)
    __shared__ float ws[64 * 72];   // [k-half][col], stride 72
    int tid = threadIdx.x;
    int lane = tid & 31, warp = tid >> 5;
    int wm = warp & 3, wn = warp >> 2;
    int gid = lane >> 2, tig = lane & 3;
    int r0 = blockIdx.x * 64;

    float4 c[4];
#pragma unroll
    for (int t = 0; t < 4; t++) c[t] = make_float4(0.f, 0.f, 0.f, 0.f);

    for (int kh = 0; kh < 2; kh++) {
#pragma unroll
        for (int q = 0; q < 4; q++) {
            int idx = tid + q * 256;           // 0..1023
            int row = idx >> 4, k4 = idx & 15;
            float4 v = make_float4(0.f, 0.f, 0.f, 0.f);
            int grow = r0 + row;
            if (grow < n)
                v = *(const float4*)(x + (size_t)grow * IN_DIM + kh * 64 + k4 * 4);
            *(float4*)(xs + row * 68 + k4 * 4) =
                make_float4(f2tf(v.x), f2tf(v.y), f2tf(v.z), f2tf(v.w));
        }
#pragma unroll
        for (int q = 0; q < 4; q++) {
            int idx = tid + q * 256;
            int k = idx >> 4, c4 = idx & 15;
            float4 v = *(const float4*)(W + (size_t)(kh * 64 + k) * HC + c4 * 4);
            *(float4*)(ws + k * 72 + c4 * 4) =
                make_float4(f2tf(v.x), f2tf(v.y), f2tf(v.z), f2tf(v.w));
        }
        __syncthreads();
#pragma unroll
        for (int k8 = 0; k8 < 8; k8++) {
            int kb = k8 * 8;
            const float* xr = xs + (16 * wm + gid) * 68 + kb + tig;
            float a0 = xr[0];
            float a1 = xr[8 * 68];
            float a2 = xr[4];
            float a3 = xr[8 * 68 + 4];
            const float* wr = ws + (kb + tig) * 72 + 32 * wn + gid;
#pragma unroll
            for (int t = 0; t < 4; t++) {
                float b0 = wr[8 * t];
                float b1 = wr[4 * 72 + 8 * t];
                mma_tf32(c[t], a0, a1, a2, a3, b0, b1);
            }
        }
        __syncthreads();
    }

    {
        int rlo = 16 * wm + gid;
        int cb  = 32 * wn + 2 * tig;
#pragma unroll
        for (int t = 0; t < 4; t++) {
            *(float2*)(xs + rlo * 68 + cb + 8 * t)       = make_float2(c[t].x, c[t].y);
            *(float2*)(xs + (rlo + 8) * 68 + cb + 8 * t) = make_float2(c[t].z, c[t].w);
        }
    }
    __syncthreads();

    {
        int row = tid >> 2, qd = tid & 3;
        int grow = r0 + row;
        if (grow < n) {
            float4 v[4], s4[4], d4[4];
#pragma unroll
            for (int i = 0; i < 4; i++) {
                v[i]  = *(const float4*)(xs + row * 68 + qd * 16 + 4 * i);
                s4[i] = __ldg((const float4*)(att_src + qd * 16 + 4 * i));
                d4[i] = __ldg((const float4*)(att_dst + qd * 16 + 4 * i));
            }
            float as = 0.f, ad = 0.f;
#pragma unroll
            for (int i = 0; i < 4; i++) {
                as += v[i].x * s4[i].x + v[i].y * s4[i].y + v[i].z * s4[i].z + v[i].w * s4[i].w;
                ad += v[i].x * d4[i].x + v[i].y * d4[i].y + v[i].z * d4[i].z + v[i].w * d4[i].w;
            }
            ((float*)&g_as4[grow])[qd] = as;
            ((float*)&g_dpk[2 * (size_t)grow])[qd] = ad;
            // xp half2 interleaved pairs: slot c in [8qd, 8qd+8): (xp[c], xp[c+32])
#pragma unroll
            for (int i = 0; i < 2; i++) {
                float4 A4 = *(const float4*)(xs + row * 68 + 8 * qd + 4 * i);
                float4 B4 = *(const float4*)(xs + row * 68 + 8 * qd + 32 + 4 * i);
                __half2 hp[4];
                hp[0] = __floats2half2_rn(A4.x, B4.x);
                hp[1] = __floats2half2_rn(A4.y, B4.y);
                hp[2] = __floats2half2_rn(A4.z, B4.z);
                hp[3] = __floats2half2_rn(A4.w, B4.w);
                *(uint4*)(g_xph + (size_t)grow * 32 + 8 * qd + 4 * i) = *(const uint4*)hp;
            }
        }
    }
}

// ---------------- histogram + fused edge_index float copy ----------------
__global__ void hist_kernel(const int* __restrict__ ei, int e, float* __restrict__ ei_out) {
    int t = blockIdx.x * blockDim.x + threadIdx.x;
    int base = t * 4;
    if (base + 3 < e) {
        int4 d4 = *(const int4*)(ei + e + base);
        atomicAdd(&g_cnt[d4.x], 1);
        atomicAdd(&g_cnt[d4.y], 1);
        atomicAdd(&g_cnt[d4.z], 1);
        atomicAdd(&g_cnt[d4.w], 1);
        if (ei_out) {
            int4 s4 = *(const int4*)(ei + base);
            *(float4*)(ei_out + base) =
                make_float4((float)s4.x, (float)s4.y, (float)s4.z, (float)s4.w);
            *(float4*)(ei_out + e + base) =
                make_float4((float)d4.x, (float)d4.y, (float)d4.z, (float)d4.w);
        }
    } else {
        for (int i = base; i < e; i++) {
            int s = ei[i], d = ei[e + i];
            atomicAdd(&g_cnt[d], 1);
            if (ei_out) { ei_out[i] = (float)s; ei_out[e + i] = (float)d; }
        }
    }
}

// ---------------- scan1: per-block inclusive scan + restore g_cnt zeros ----------------
__global__ void scan1_kernel(int n) {
    __shared__ int sd[512];
    int t = threadIdx.x, i = blockIdx.x * 512 + t;
    int v = 0;
    if (i < n) { v = g_cnt[i]; g_cnt[i] = 0; }   // restore zero-invariant for next call
    sd[t] = v; __syncthreads();
    for (int off = 1; off < 512; off <<= 1) {
        int x = (t >= off) ? sd[t - off] : 0;
        __syncthreads();
        sd[t] += x;
        __syncthreads();
    }
    if (i < n) g_rowptr[i + 1] = sd[t];
    if (t == 511) g_bsum[blockIdx.x] = sd[511];
}

// ---------------- scan23: spine reduce + apply offsets + init absolute cursors ---------
__global__ void scan23_kernel(int n) {
    __shared__ int sd[512];
    int t = threadIdx.x;
    int v = (t < blockIdx.x) ? g_bsum[t] : 0;     // blockIdx.x <= 195 < 512
    sd[t] = v; __syncthreads();
#pragma unroll
    for (int off = 256; off >= 1; off >>= 1) {
        if (t < off) sd[t] += sd[t + off];
        __syncthreads();
    }
    int inc = sd[0];                              // exclusive spine prefix for this block
    int i = blockIdx.x * 512 + t;
    int prev = 0;
    if (i < n && t > 0) prev = g_rowptr[i];       // scan1 value at i (pre-offset)
    __syncthreads();
    if (i < n) {
        g_rowptr[i + 1] += inc;
        g_fill[i] = prev + inc;                   // absolute start
        if (i == 0) g_rowptr[0] = 0;
    }
}

// 8 edges/thread; atomic returns absolute CSR position (no dependent load)
__global__ void fill_kernel(const int* __restrict__ ei, int e) {
    int t = blockIdx.x * blockDim.x + threadIdx.x;
    int base = t * 8;
    if (base + 7 < e) {
        int4 sa = *(const int4*)(ei + base);
        int4 sb = *(const int4*)(ei + base + 4);
        int4 da = *(const int4*)(ei + e + base);
        int4 db = *(const int4*)(ei + e + base + 4);
        int p0 = atomicAdd(&g_fill[da.x], 1);
        int p1 = atomicAdd(&g_fill[da.y], 1);
        int p2 = atomicAdd(&g_fill[da.z], 1);
        int p3 = atomicAdd(&g_fill[da.w], 1);
        int p4 = atomicAdd(&g_fill[db.x], 1);
        int p5 = atomicAdd(&g_fill[db.y], 1);
        int p6 = atomicAdd(&g_fill[db.z], 1);
        int p7 = atomicAdd(&g_fill[db.w], 1);
        g_csr2[p0] = make_int2(sa.x, base + 0);
        g_csr2[p1] = make_int2(sa.y, base + 1);
        g_csr2[p2] = make_int2(sa.z, base + 2);
        g_csr2[p3] = make_int2(sa.w, base + 3);
        g_csr2[p4] = make_int2(sb.x, base + 4);
        g_csr2[p5] = make_int2(sb.y, base + 5);
        g_csr2[p6] = make_int2(sb.z, base + 6);
        g_csr2[p7] = make_int2(sb.w, base + 7);
    } else {
        for (int i = base; i < e; i++) {
            int s = ei[i], d = ei[e + i];
            int pos = atomicAdd(&g_fill[d], 1);
            g_csr2[pos] = make_int2(s, i);
        }
    }
}

// ---------------- fused softmax + aggregation + raw-alpha scatter ----------------
__global__ __launch_bounds__(256) void aggregate_kernel(
    const float* __restrict__ bias, float* __restrict__ out,
    float* __restrict__ alpha_out, int n)
{
    __shared__ float sE[8][32][4];
    int w = (blockIdx.x * 256 + threadIdx.x) >> 5;
    int lane = threadIdx.x & 31, wl = threadIdx.x >> 5;
    if (w >= n) return;                 // uniform per warp

    int start = g_rowptr[w];
    int deg   = g_rowptr[w + 1] - start;
    float4 ad = g_dpk[2 * (size_t)w];

    float4 ds = make_float4(0.f, 0.f, 0.f, 0.f);
    float acc0 = 0.f, acc1 = 0.f;
    int h0 = lane >> 4;      // head of col=lane; col=lane+32 is head h0+2

    for (int base = 0; base < deg; base += 32) {
        int i = base + lane;
        int s = 0;
        float4 ev = make_float4(0.f, 0.f, 0.f, 0.f);
        if (i < deg) {
            int2 se = g_csr2[start + i];
            s = se.x;
            float4 a = g_as4[s];
            ev.x = __expf(lrelu(a.x + ad.x));
            ev.y = __expf(lrelu(a.y + ad.y));
            ev.z = __expf(lrelu(a.z + ad.z));
            ev.w = __expf(lrelu(a.w + ad.w));
            ds.x += ev.x; ds.y += ev.y; ds.z += ev.z; ds.w += ev.w;
            if (alpha_out) ((float4*)alpha_out)[se.y] = ev;   // raw, scaled later
        }
        sE[wl][lane][0] = ev.x; sE[wl][lane][1] = ev.y;
        sE[wl][lane][2] = ev.z; sE[wl][lane][3] = ev.w;
        __syncwarp();
        int cnt = min(32, deg - base);
        const float* sEj = &sE[wl][0][0];
#pragma unroll 8
        for (int j = 0; j < cnt; j++) {
            int sj = __shfl_sync(0xffffffffu, s, j);
            float e0 = sEj[j * 4 + h0];
            float e1 = sEj[j * 4 + 2 + h0];
            float2 f = __half22float2(__ldg(g_xph + (size_t)sj * 32 + lane));
            acc0 = fmaf(f.x, e0, acc0);
            acc1 = fmaf(f.y, e1, acc1);
        }
        __syncwarp();
    }
#pragma unroll
    for (int o = 16; o >= 1; o >>= 1) {
        ds.x += __shfl_xor_sync(0xffffffffu, ds.x, o);
        ds.y += __shfl_xor_sync(0xffffffffu, ds.y, o);
        ds.z += __shfl_xor_sync(0xffffffffu, ds.z, o);
        ds.w += __shfl_xor_sync(0xffffffffu, ds.w, o);
    }
    float4 r;
    r.x = 1.f / (ds.x + 1e-16f); r.y = 1.f / (ds.y + 1e-16f);
    r.z = 1.f / (ds.z + 1e-16f); r.w = 1.f / (ds.w + 1e-16f);
    if (lane == 0) g_dpk[2 * (size_t)w + 1] = r;

    float r0 = h0 ? r.y : r.x;
    float r1 = h0 ? r.w : r.z;
    out[(size_t)w * HC + lane]      = acc0 * r0 + bias[lane];
    out[(size_t)w * HC + 32 + lane] = acc1 * r1 + bias[lane + 32];
}

// ---------------- alpha scale: alpha[t] *= rcp[dst[t]] (coalesced + 1 gather) ----------
__global__ __launch_bounds__(256) void alpha_scale_kernel(
    const int* __restrict__ ei, int e, float* __restrict__ alpha_out)
{
    int t = blockIdx.x * blockDim.x + threadIdx.x;
    if (t >= e) return;
    int d = ei[e + t];
    float4 r = g_dpk[2 * (size_t)d + 1];
    float4 a = ((const float4*)alpha_out)[t];
    a.x *= r.x; a.y *= r.y; a.z *= r.z; a.w *= r.w;
    ((float4*)alpha_out)[t] = a;
}

extern "C" void kernel_launch(void* const* d_in, const int* in_sizes, int n_in,
                              void* d_out, int out_size) {
    const float* x       = (const float*)d_in[0];
    const float* W       = (const float*)d_in[1];
    const float* att_src = (const float*)d_in[2];
    const float* att_dst = (const float*)d_in[3];
    const float* bias    = (const float*)d_in[4];
    const int*   ei      = (const int*)d_in[5];
    float* out = (float*)d_out;

    int n = in_sizes[0] / IN_DIM;   // 100000
    int e = in_sizes[5] / 2;        // 1600000
    long nhc = (long)n * HC;
    int nb = (n + 511) / 512;

    float* ei_out = nullptr;
    float* alpha_out = nullptr;
    if ((long)out_size >= nhc + 2L * e)          ei_out    = out + nhc;
    if ((long)out_size >= nhc + 2L * e + 4L * e) alpha_out = out + nhc + 2L * e;

    int GB = (n + 63) / 64;                     // gemm blocks
    int HB = ((e + 3) / 4 + 255) / 256;         // hist blocks

    // Fork: gemm (node pipeline) on side stream; edge pipeline on main stream.
    cudaStream_t s1;
    cudaStreamCreateWithFlags(&s1, cudaStreamNonBlocking);
    cudaEvent_t evFork, evJoin;
    cudaEventCreateWithFlags(&evFork, cudaEventDisableTiming);
    cudaEventCreateWithFlags(&evJoin, cudaEventDisableTiming);

    cudaEventRecord(evFork, 0);
    cudaStreamWaitEvent(s1, evFork, 0);

    gemm_kernel<<<GB, 256, 0, s1>>>(x, W, att_src, att_dst, n);

    hist_kernel<<<HB, 256>>>(ei, e, ei_out);
    scan1_kernel<<<nb, 512>>>(n);
    scan23_kernel<<<nb, 512>>>(n);
    fill_kernel<<<((e + 7) / 8 + 255) / 256, 256>>>(ei, e);

    cudaEventRecord(evJoin, s1);
    cudaStreamWaitEvent(0, evJoin, 0);

    aggregate_kernel<<<(n * 32 + 255) / 256, 256>>>(bias, out, alpha_out, n);
    if (alpha_out)
        alpha_scale_kernel<<<(e + 255) / 256, 256>>>(ei, e, alpha_out);

    cudaEventDestroy(evFork);
    cudaEventDestroy(evJoin);
    cudaStreamDestroy(s1);
}

// round 16
// speedup vs baseline: 1.0220x; 1.0220x over previous
#include <cuda_runtime.h>
#include <cuda_fp16.h>
#include <math.h>

#define NN 100000
#define EE 1600000
#define HC 64
#define IN_DIM 128

// ---------------- scratch (device globals, allocation-free) ----------------
// g_xph holds xp in fp16 interleaved-pair layout:
//   half2 slot c (c=0..31) of node v = (xp[v][c], xp[v][c+32])
static __device__ __half2 g_xph[(size_t)NN * 32];
static __device__ float4 g_as4[NN];               // a_src [N,4]
static __device__ float4 g_dpk[2 * NN];           // [2d]=a_dst, [2d+1]=rcp (adjacent gathers)
static __device__ int    g_cnt[NN];               // degree histogram (zero-invariant between calls)
static __device__ int    g_rowptr[NN + 1];        // CSR row pointers
static __device__ int    g_bsum[512];             // scan partials
static __device__ int    g_rank[EE];              // per-edge rank within dst (from hist atomic)
static __device__ int2   g_csr2[EE];              // CSR {src, edge_id}

__device__ __forceinline__ float lrelu(float v) { return v >= 0.f ? v : 0.2f * v; }

__device__ __forceinline__ float f2tf(float f) {
    unsigned u;
    asm("cvt.rna.tf32.f32 %0, %1;" : "=r"(u) : "f"(f));
    return __uint_as_float(u);
}
__device__ __forceinline__ void mma_tf32(float4& d,
    float a0, float a1, float a2, float a3, float b0, float b1)
{
    asm("mma.sync.aligned.m16n8k8.row.col.f32.tf32.tf32.f32 "
        "{%0,%1,%2,%3}, {%4,%5,%6,%7}, {%8,%9}, {%0,%1,%2,%3};"
        : "+f"(d.x), "+f"(d.y), "+f"(d.z), "+f"(d.w)
        : "r"(__float_as_uint(a0)), "r"(__float_as_uint(a1)),
          "r"(__float_as_uint(a2)), "r"(__float_as_uint(a3)),
          "r"(__float_as_uint(b0)), "r"(__float_as_uint(b1)));
}

// ---------------- GEMM: xp = x @ W via tf32 tensor cores + attn/fp16 epilogue ----------
__global__ __launch_bounds__(256) void gemm_kernel(
    const float* __restrict__ x, const float* __restrict__ W,
    const float* __restrict__ att_src, const float* __restrict__ att_dst, int n)
{
    __shared__ float xs[64 * 68];   // [row][k-half], stride 68 (reused for C)
    __shared__ float ws[64 * 72];   // [k-half][col], stride 72
    int tid = threadIdx.x;
    int lane = tid & 31, warp = tid >> 5;
    int wm = warp & 3, wn = warp >> 2;
    int gid = lane >> 2, tig = lane & 3;
    int r0 = blockIdx.x * 64;

    float4 c[4];
#pragma unroll
    for (int t = 0; t < 4; t++) c[t] = make_float4(0.f, 0.f, 0.f, 0.f);

    for (int kh = 0; kh < 2; kh++) {
#pragma unroll
        for (int q = 0; q < 4; q++) {
            int idx = tid + q * 256;           // 0..1023
            int row = idx >> 4, k4 = idx & 15;
            float4 v = make_float4(0.f, 0.f, 0.f, 0.f);
            int grow = r0 + row;
            if (grow < n)
                v = *(const float4*)(x + (size_t)grow * IN_DIM + kh * 64 + k4 * 4);
            *(float4*)(xs + row * 68 + k4 * 4) =
                make_float4(f2tf(v.x), f2tf(v.y), f2tf(v.z), f2tf(v.w));
        }
#pragma unroll
        for (int q = 0; q < 4; q++) {
            int idx = tid + q * 256;
            int k = idx >> 4, c4 = idx & 15;
            float4 v = *(const float4*)(W + (size_t)(kh * 64 + k) * HC + c4 * 4);
            *(float4*)(ws + k * 72 + c4 * 4) =
                make_float4(f2tf(v.x), f2tf(v.y), f2tf(v.z), f2tf(v.w));
        }
        __syncthreads();
#pragma unroll
        for (int k8 = 0; k8 < 8; k8++) {
            int kb = k8 * 8;
            const float* xr = xs + (16 * wm + gid) * 68 + kb + tig;
            float a0 = xr[0];
            float a1 = xr[8 * 68];
            float a2 = xr[4];
            float a3 = xr[8 * 68 + 4];
            const float* wr = ws + (kb + tig) * 72 + 32 * wn + gid;
#pragma unroll
            for (int t = 0; t < 4; t++) {
                float b0 = wr[8 * t];
                float b1 = wr[4 * 72 + 8 * t];
                mma_tf32(c[t], a0, a1, a2, a3, b0, b1);
            }
        }
        __syncthreads();
    }

    {
        int rlo = 16 * wm + gid;
        int cb  = 32 * wn + 2 * tig;
#pragma unroll
        for (int t = 0; t < 4; t++) {
            *(float2*)(xs + rlo * 68 + cb + 8 * t)       = make_float2(c[t].x, c[t].y);
            *(float2*)(xs + (rlo + 8) * 68 + cb + 8 * t) = make_float2(c[t].z, c[t].w);
        }
    }
    __syncthreads();

    {
        int row = tid >> 2, qd = tid & 3;
        int grow = r0 + row;
        if (grow < n) {
            float4 v[4], s4[4], d4[4];
#pragma unroll
            for (int i = 0; i < 4; i++) {
                v[i]  = *(const float4*)(xs + row * 68 + qd * 16 + 4 * i);
                s4[i] = __ldg((const float4*)(att_src + qd * 16 + 4 * i));
                d4[i] = __ldg((const float4*)(att_dst + qd * 16 + 4 * i));
            }
            float as = 0.f, ad = 0.f;
#pragma unroll
            for (int i = 0; i < 4; i++) {
                as += v[i].x * s4[i].x + v[i].y * s4[i].y + v[i].z * s4[i].z + v[i].w * s4[i].w;
                ad += v[i].x * d4[i].x + v[i].y * d4[i].y + v[i].z * d4[i].z + v[i].w * d4[i].w;
            }
            ((float*)&g_as4[grow])[qd] = as;
            ((float*)&g_dpk[2 * (size_t)grow])[qd] = ad;
            // xp half2 interleaved pairs: slot c in [8qd, 8qd+8): (xp[c], xp[c+32])
#pragma unroll
            for (int i = 0; i < 2; i++) {
                float4 A4 = *(const float4*)(xs + row * 68 + 8 * qd + 4 * i);
                float4 B4 = *(const float4*)(xs + row * 68 + 8 * qd + 32 + 4 * i);
                __half2 hp[4];
                hp[0] = __floats2half2_rn(A4.x, B4.x);
                hp[1] = __floats2half2_rn(A4.y, B4.y);
                hp[2] = __floats2half2_rn(A4.z, B4.z);
                hp[3] = __floats2half2_rn(A4.w, B4.w);
                *(uint4*)(g_xph + (size_t)grow * 32 + 8 * qd + 4 * i) = *(const uint4*)hp;
            }
        }
    }
}

// ---------------- histogram (records per-edge rank) + edge_index float copy ------------
__global__ void hist_kernel(const int* __restrict__ ei, int e, float* __restrict__ ei_out) {
    int t = blockIdx.x * blockDim.x + threadIdx.x;
    int base = t * 4;
    if (base + 3 < e) {
        int4 d4 = *(const int4*)(ei + e + base);
        int4 r4;
        r4.x = atomicAdd(&g_cnt[d4.x], 1);
        r4.y = atomicAdd(&g_cnt[d4.y], 1);
        r4.z = atomicAdd(&g_cnt[d4.z], 1);
        r4.w = atomicAdd(&g_cnt[d4.w], 1);
        *(int4*)(g_rank + base) = r4;
        if (ei_out) {
            int4 s4 = *(const int4*)(ei + base);
            *(float4*)(ei_out + base) =
                make_float4((float)s4.x, (float)s4.y, (float)s4.z, (float)s4.w);
            *(float4*)(ei_out + e + base) =
                make_float4((float)d4.x, (float)d4.y, (float)d4.z, (float)d4.w);
        }
    } else {
        for (int i = base; i < e; i++) {
            int s = ei[i], d = ei[e + i];
            g_rank[i] = atomicAdd(&g_cnt[d], 1);
            if (ei_out) { ei_out[i] = (float)s; ei_out[e + i] = (float)d; }
        }
    }
}

// ---------------- scan1: per-block inclusive scan + restore g_cnt zeros ----------------
__global__ void scan1_kernel(int n) {
    __shared__ int sd[512];
    int t = threadIdx.x, i = blockIdx.x * 512 + t;
    int v = 0;
    if (i < n) { v = g_cnt[i]; g_cnt[i] = 0; }   // restore zero-invariant for next call
    sd[t] = v; __syncthreads();
    for (int off = 1; off < 512; off <<= 1) {
        int x = (t >= off) ? sd[t - off] : 0;
        __syncthreads();
        sd[t] += x;
        __syncthreads();
    }
    if (i < n) g_rowptr[i + 1] = sd[t];
    if (t == 511) g_bsum[blockIdx.x] = sd[511];
}

// ---------------- scan23: spine reduce + apply offsets ----------------
__global__ void scan23_kernel(int n) {
    __shared__ int sd[512];
    int t = threadIdx.x;
    int v = (t < blockIdx.x) ? g_bsum[t] : 0;     // blockIdx.x <= 195 < 512
    sd[t] = v; __syncthreads();
#pragma unroll
    for (int off = 256; off >= 1; off >>= 1) {
        if (t < off) sd[t] += sd[t + off];
        __syncthreads();
    }
    int inc = sd[0];                              // exclusive spine prefix for this block
    int i = blockIdx.x * 512 + t;
    if (i < n) {
        g_rowptr[i + 1] += inc;
        if (i == 0) g_rowptr[0] = 0;
    }
}

// atomic-free fill: pos = rowptr[dst] + rank (rank recorded by hist)
__global__ void fill_kernel(const int* __restrict__ ei, int e) {
    int t = blockIdx.x * blockDim.x + threadIdx.x;
    int base = t * 4;
    if (base + 3 < e) {
        int4 s4 = *(const int4*)(ei + base);
        int4 d4 = *(const int4*)(ei + e + base);
        int4 r4 = *(const int4*)(g_rank + base);
        int p0 = g_rowptr[d4.x] + r4.x;
        int p1 = g_rowptr[d4.y] + r4.y;
        int p2 = g_rowptr[d4.z] + r4.z;
        int p3 = g_rowptr[d4.w] + r4.w;
        g_csr2[p0] = make_int2(s4.x, base + 0);
        g_csr2[p1] = make_int2(s4.y, base + 1);
        g_csr2[p2] = make_int2(s4.z, base + 2);
        g_csr2[p3] = make_int2(s4.w, base + 3);
    } else {
        for (int i = base; i < e; i++) {
            int s = ei[i], d = ei[e + i];
            g_csr2[g_rowptr[d] + g_rank[i]] = make_int2(s, i);
        }
    }
}

// ---------------- fused softmax + aggregation + raw-alpha scatter ----------------
__global__ __launch_bounds__(256) void aggregate_kernel(
    const float* __restrict__ bias, float* __restrict__ out,
    float* __restrict__ alpha_out, int n)
{
    __shared__ float sE[8][32][4];
    int w = (blockIdx.x * 256 + threadIdx.x) >> 5;
    int lane = threadIdx.x & 31, wl = threadIdx.x >> 5;
    if (w >= n) return;                 // uniform per warp

    int start = g_rowptr[w];
    int deg   = g_rowptr[w + 1] - start;
    float4 ad = g_dpk[2 * (size_t)w];

    float4 ds = make_float4(0.f, 0.f, 0.f, 0.f);
    float acc0 = 0.f, acc1 = 0.f;
    int h0 = lane >> 4;      // head of col=lane; col=lane+32 is head h0+2

    for (int base = 0; base < deg; base += 32) {
        int i = base + lane;
        int s = 0;
        float4 ev = make_float4(0.f, 0.f, 0.f, 0.f);
        if (i < deg) {
            int2 se = g_csr2[start + i];
            s = se.x;
            float4 a = g_as4[s];
            ev.x = __expf(lrelu(a.x + ad.x));
            ev.y = __expf(lrelu(a.y + ad.y));
            ev.z = __expf(lrelu(a.z + ad.z));
            ev.w = __expf(lrelu(a.w + ad.w));
            ds.x += ev.x; ds.y += ev.y; ds.z += ev.z; ds.w += ev.w;
            if (alpha_out) ((float4*)alpha_out)[se.y] = ev;   // raw, scaled later
        }
        sE[wl][lane][0] = ev.x; sE[wl][lane][1] = ev.y;
        sE[wl][lane][2] = ev.z; sE[wl][lane][3] = ev.w;
        __syncwarp();
        int cnt = min(32, deg - base);
        const float* sEj = &sE[wl][0][0];
#pragma unroll 8
        for (int j = 0; j < cnt; j++) {
            int sj = __shfl_sync(0xffffffffu, s, j);
            float e0 = sEj[j * 4 + h0];
            float e1 = sEj[j * 4 + 2 + h0];
            float2 f = __half22float2(__ldg(g_xph + (size_t)sj * 32 + lane));
            acc0 = fmaf(f.x, e0, acc0);
            acc1 = fmaf(f.y, e1, acc1);
        }
        __syncwarp();
    }
#pragma unroll
    for (int o = 16; o >= 1; o >>= 1) {
        ds.x += __shfl_xor_sync(0xffffffffu, ds.x, o);
        ds.y += __shfl_xor_sync(0xffffffffu, ds.y, o);
        ds.z += __shfl_xor_sync(0xffffffffu, ds.z, o);
        ds.w += __shfl_xor_sync(0xffffffffu, ds.w, o);
    }
    float4 r;
    r.x = 1.f / (ds.x + 1e-16f); r.y = 1.f / (ds.y + 1e-16f);
    r.z = 1.f / (ds.z + 1e-16f); r.w = 1.f / (ds.w + 1e-16f);
    if (lane == 0) g_dpk[2 * (size_t)w + 1] = r;

    float r0 = h0 ? r.y : r.x;
    float r1 = h0 ? r.w : r.z;
    out[(size_t)w * HC + lane]      = acc0 * r0 + bias[lane];
    out[(size_t)w * HC + 32 + lane] = acc1 * r1 + bias[lane + 32];
}

// ---------------- alpha scale: alpha[t] *= rcp[dst[t]] (coalesced + 1 gather) ----------
__global__ __launch_bounds__(256) void alpha_scale_kernel(
    const int* __restrict__ ei, int e, float* __restrict__ alpha_out)
{
    int t = blockIdx.x * blockDim.x + threadIdx.x;
    if (t >= e) return;
    int d = ei[e + t];
    float4 r = g_dpk[2 * (size_t)d + 1];
    float4 a = ((const float4*)alpha_out)[t];
    a.x *= r.x; a.y *= r.y; a.z *= r.z; a.w *= r.w;
    ((float4*)alpha_out)[t] = a;
}

extern "C" void kernel_launch(void* const* d_in, const int* in_sizes, int n_in,
                              void* d_out, int out_size) {
    const float* x       = (const float*)d_in[0];
    const float* W       = (const float*)d_in[1];
    const float* att_src = (const float*)d_in[2];
    const float* att_dst = (const float*)d_in[3];
    const float* bias    = (const float*)d_in[4];
    const int*   ei      = (const int*)d_in[5];
    float* out = (float*)d_out;

    int n = in_sizes[0] / IN_DIM;   // 100000
    int e = in_sizes[5] / 2;        // 1600000
    long nhc = (long)n * HC;
    int nb = (n + 511) / 512;

    float* ei_out = nullptr;
    float* alpha_out = nullptr;
    if ((long)out_size >= nhc + 2L * e)          ei_out    = out + nhc;
    if ((long)out_size >= nhc + 2L * e + 4L * e) alpha_out = out + nhc + 2L * e;

    int GB = (n + 63) / 64;                     // gemm blocks
    int HB = ((e + 3) / 4 + 255) / 256;         // hist blocks

    // Fork: gemm (node pipeline) on side stream; edge pipeline on main stream.
    cudaStream_t s1;
    cudaStreamCreateWithFlags(&s1, cudaStreamNonBlocking);
    cudaEvent_t evFork, evJoin;
    cudaEventCreateWithFlags(&evFork, cudaEventDisableTiming);
    cudaEventCreateWithFlags(&evJoin, cudaEventDisableTiming);

    cudaEventRecord(evFork, 0);
    cudaStreamWaitEvent(s1, evFork, 0);

    gemm_kernel<<<GB, 256, 0, s1>>>(x, W, att_src, att_dst, n);

    hist_kernel<<<HB, 256>>>(ei, e, ei_out);
    scan1_kernel<<<nb, 512>>>(n);
    scan23_kernel<<<nb, 512>>>(n);
    fill_kernel<<<HB, 256>>>(ei, e);

    cudaEventRecord(evJoin, s1);
    cudaStreamWaitEvent(0, evJoin, 0);

    aggregate_kernel<<<(n * 32 + 255) / 256, 256>>>(bias, out, alpha_out, n);
    if (alpha_out)
        alpha_scale_kernel<<<(e + 255) / 256, 256>>>(ei, e, alpha_out);

    cudaEventDestroy(evFork);
    cudaEventDestroy(evJoin);
    cudaStreamDestroy(s1);
}